// round 9
// baseline (speedup 1.0000x reference)
#include <cuda_runtime.h>
#include <math.h>

// ---------------------------------------------------------------------------
// ImageSectionRNNCell — B=64, image 512x512x3, grid 16x16, U=256
// out layout: h_new[64*256] | c_new[64*256] | next_section[64*3]
//
// 5 launches:
//  K1 (64):  front (interp+conv1+conv2 -> g_xs) + bias-init g_y/g_ns
//  K2 (128): dense partial xs@dw -> g_y (atomicAdd, bias-pre-init)
//  K3 (128): LSTM full-K: block j owns units {2j,2j+1} (8 z-cols), K=512,
//            gates fused in epilogue -> out h/c. No partial buffers.
//  K5 (64):  nsc1 partial h@w1 -> g_ns (atomicAdd, bias-pre-init)
//  K6 (64):  nsc2 -> out section
// ---------------------------------------------------------------------------

#define B 64
#define U 256
#define IMGH 512
#define IMGW 512

__device__ float g_xs[B * 432];     // conv2 output (dense input)
__device__ float g_y [B * U];       // dense pre-act accumulator (bias-init K1)
__device__ float g_ns[B * U];       // nsc1 pre-act accumulator (bias-init K1)

__device__ __forceinline__ float sigmoidf_(float x) {
    return 1.0f / (1.0f + __expf(-x));
}

// ===========================================================================
// K1: bias-init g_y/g_ns + interpolate + conv1 + conv2 -> g_xs
// 64 blocks (one per batch) x 256 threads, small static smem (occ 4)
// ===========================================================================
__global__ __launch_bounds__(256, 4)
void k1_front(const float* __restrict__ image,
              const float* __restrict__ section,
              const float* __restrict__ c1k, const float* __restrict__ c1b,
              const float* __restrict__ c2k, const float* __restrict__ c2b,
              const float* __restrict__ db,  const float* __restrict__ b1)
{
    const int b = blockIdx.x;
    const int t = threadIdx.x;

    g_y [b * U + t] = db[t];
    g_ns[b * U + t] = b1[t];

    __shared__ float sec[16 * 16 * 3];
    __shared__ float c1o[14 * 14 * 3];

    {
        const float s0 = section[b * 3 + 0];
        const float s1 = section[b * 3 + 1];
        const float ee = section[b * 3 + 2];
        const int i = t >> 4;
        const int j = t & 15;
        const float p0 = s0 + (float)i * (1.0f / 15.0f) * ee;
        const float p1 = s1 + (float)j * (1.0f / 15.0f) * ee;
        float fy = fminf(fmaxf(p0 * (float)(IMGH - 1), 0.0f), (float)(IMGH - 1));
        float fx = fminf(fmaxf(p1 * (float)(IMGW - 1), 0.0f), (float)(IMGW - 1));
        int y0 = (int)floorf(fy);
        int x0 = (int)floorf(fx);
        int y1 = min(y0 + 1, IMGH - 1);
        int x1 = min(x0 + 1, IMGW - 1);
        float wy = fy - (float)y0;
        float wx = fx - (float)x0;
        const float* img = image + (size_t)b * IMGH * IMGW * 3;
        const float* p00 = img + ((size_t)y0 * IMGW + x0) * 3;
        const float* p01 = img + ((size_t)y0 * IMGW + x1) * 3;
        const float* p10 = img + ((size_t)y1 * IMGW + x0) * 3;
        const float* p11 = img + ((size_t)y1 * IMGW + x1) * 3;
        #pragma unroll
        for (int c = 0; c < 3; c++) {
            float top = p00[c] * (1.0f - wx) + p01[c] * wx;
            float bot = p10[c] * (1.0f - wx) + p11[c] * wx;
            sec[(i * 16 + j) * 3 + c] = top * (1.0f - wy) + bot * wy;
        }
    }
    __syncthreads();

    if (t < 196) {
        const int oh = t / 14;
        const int ow = t - oh * 14;
        float a0 = c1b[0], a1 = c1b[1], a2 = c1b[2];
        #pragma unroll
        for (int kh = 0; kh < 3; kh++)
            #pragma unroll
            for (int kw = 0; kw < 3; kw++) {
                const float* s = &sec[((oh + kh) * 16 + (ow + kw)) * 3];
                const float* w = &c1k[(kh * 3 + kw) * 9];
                #pragma unroll
                for (int ic = 0; ic < 3; ic++) {
                    const float sv = s[ic];
                    a0 += sv * w[ic * 3 + 0];
                    a1 += sv * w[ic * 3 + 1];
                    a2 += sv * w[ic * 3 + 2];
                }
            }
        c1o[t * 3 + 0] = fmaxf(a0, 0.0f);
        c1o[t * 3 + 1] = fmaxf(a1, 0.0f);
        c1o[t * 3 + 2] = fmaxf(a2, 0.0f);
    }
    __syncthreads();

    if (t < 144) {
        const int oh = t / 12;
        const int ow = t - oh * 12;
        float a0 = c2b[0], a1 = c2b[1], a2 = c2b[2];
        #pragma unroll
        for (int kh = 0; kh < 3; kh++)
            #pragma unroll
            for (int kw = 0; kw < 3; kw++) {
                const float* s = &c1o[((oh + kh) * 14 + (ow + kw)) * 3];
                const float* w = &c2k[(kh * 3 + kw) * 9];
                #pragma unroll
                for (int ic = 0; ic < 3; ic++) {
                    const float sv = s[ic];
                    a0 += sv * w[ic * 3 + 0];
                    a1 += sv * w[ic * 3 + 1];
                    a2 += sv * w[ic * 3 + 2];
                }
            }
        float* dst = g_xs + b * 432 + t * 3;
        dst[0] = fmaxf(a0, 0.0f);
        dst[1] = fmaxf(a1, 0.0f);
        dst[2] = fmaxf(a2, 0.0f);
    }
}

// ===========================================================================
// K2: dense partial. 128 blocks = 32 unit-tiles (8 units) x 4 k-tiles (108).
// atomicAdd into g_y (bias pre-initialized). ReLU applied by consumer (K3).
// ===========================================================================
__global__ __launch_bounds__(256, 1)
void k2_dense(const float* __restrict__ dw)
{
    const int ut = blockIdx.x & 31;
    const int kt = blockIdx.x >> 5;
    const int t  = threadIdx.x;
    const int k0 = kt * 108;

    __shared__ float axs[64][112];
    __shared__ float wts[108][12];

    for (int i = t; i < 64 * 27; i += 256) {
        const int row = i / 27;
        const int c4  = i - row * 27;
        const float4 v = *(const float4*)(g_xs + row * 432 + k0 + c4 * 4);
        *(float4*)&axs[row][c4 * 4] = v;
    }
    if (t < 216) {
        const int row = t >> 1;
        const int h   = t & 1;
        const float4 w = *(const float4*)(dw + (size_t)(k0 + row) * U + ut * 8 + h * 4);
        *(float4*)&wts[row][h * 4] = w;
    }
    __syncthreads();

    const int u2 = t & 3;
    const int bp = t >> 2;
    float a0 = 0.f, a1 = 0.f, a2 = 0.f, a3 = 0.f;
    #pragma unroll 2
    for (int k = 0; k < 108; k += 2) {
        const float x0 = axs[bp][k];
        const float x1 = axs[bp][k + 1];
        const float2 w0 = *(const float2*)&wts[k][u2 * 2];
        const float2 w1 = *(const float2*)&wts[k + 1][u2 * 2];
        a0 += x0 * w0.x; a1 += x0 * w0.y;
        a2 += x1 * w1.x; a3 += x1 * w1.y;
    }
    const int u = ut * 8 + u2 * 2;
    atomicAdd(&g_y[bp * U + u],     a0 + a2);
    atomicAdd(&g_y[bp * U + u + 1], a1 + a3);
}

// ===========================================================================
// K3: LSTM full-K + fused gates. Block j owns units {2j, 2j+1} -> 8 z-cols
// (4 gates x 2 units) for all 64 batches. K = 512 in 4 chunks of 128:
//   ch 0,1: acts = relu(g_y)  weights = lstm_k
//   ch 2,3: acts = h0         weights = lstm_rk
// Epilogue computes the gate nonlinearity and writes h_new/c_new directly.
// ===========================================================================
__global__ __launch_bounds__(256, 1)
void k3_lstm_full(const float* __restrict__ h0, const float* __restrict__ c0in,
                  const float* __restrict__ lk, const float* __restrict__ lrk,
                  const float* __restrict__ lb, float* __restrict__ out)
{
    const int j = blockIdx.x;      // unit pair
    const int t = threadIdx.x;

    __shared__ float act[64][132];     // act chunk [batch][k]
    __shared__ float wt[8][132];       // weight chunk transposed [col][k]
    __shared__ float zs[64][8];

    const int cp = t & 3;              // gate index (0..3)
    const int bp = t >> 2;             // batch (0..63)
    const int c0i = 2 * cp, c1i = 2 * cp + 1;

    float a00 = 0.f, a01 = 0.f, a10 = 0.f, a11 = 0.f;

    for (int ch = 0; ch < 4; ch++) {
        const bool fromY = (ch < 2);
        // act chunk: 64 rows x 128 floats
        {
            const float* src = fromY ? (g_y + ch * 128) : (h0 + (ch - 2) * 128);
            for (int i = t; i < 64 * 32; i += 256) {
                const int row = i >> 5;
                const int c4  = i & 31;
                float4 v = *(const float4*)(src + row * U + c4 * 4);
                if (fromY) {
                    v.x = fmaxf(v.x, 0.f); v.y = fmaxf(v.y, 0.f);
                    v.z = fmaxf(v.z, 0.f); v.w = fmaxf(v.w, 0.f);
                }
                *(float4*)&act[row][c4 * 4] = v;
            }
        }
        // weight chunk: k-row t (t<128), 2 cols per gate
        if (t < 128) {
            const float* wsrc = fromY ? lk : lrk;
            const int krow = (fromY ? ch : (ch - 2)) * 128 + t;
            const float* wr = wsrc + (size_t)krow * (4 * U) + 2 * j;
            #pragma unroll
            for (int g = 0; g < 4; g++) {
                const float2 wv = *(const float2*)(wr + g * U);
                wt[2 * g + 0][t] = wv.x;
                wt[2 * g + 1][t] = wv.y;
            }
        }
        __syncthreads();

        const float* xr  = &act[bp][0];
        const float* w0r = &wt[c0i][0];
        const float* w1r = &wt[c1i][0];
        #pragma unroll
        for (int kk = 0; kk < 128; kk += 8) {
            const float4 x0 = *(const float4*)(xr + kk);
            const float4 u0 = *(const float4*)(w0r + kk);
            const float4 v0 = *(const float4*)(w1r + kk);
            a00 += x0.x * u0.x + x0.y * u0.y + x0.z * u0.z + x0.w * u0.w;
            a10 += x0.x * v0.x + x0.y * v0.y + x0.z * v0.z + x0.w * v0.w;
            const float4 x1 = *(const float4*)(xr + kk + 4);
            const float4 u1 = *(const float4*)(w0r + kk + 4);
            const float4 v1 = *(const float4*)(w1r + kk + 4);
            a01 += x1.x * u1.x + x1.y * u1.y + x1.z * u1.z + x1.w * u1.w;
            a11 += x1.x * v1.x + x1.y * v1.y + x1.z * v1.z + x1.w * v1.w;
        }
        __syncthreads();
    }

    zs[bp][c0i] = a00 + a01 + lb[cp * U + 2 * j + 0];
    zs[bp][c1i] = a10 + a11 + lb[cp * U + 2 * j + 1];
    __syncthreads();

    if (t < 128) {
        const int bb = t >> 1;
        const int d  = t & 1;
        const int u  = 2 * j + d;
        const float iz = zs[bb][0 + d];
        const float fz = zs[bb][2 + d];
        const float gz = zs[bb][4 + d];
        const float oz = zs[bb][6 + d];
        const float cprev = c0in[bb * U + u];
        const float cn = sigmoidf_(fz) * cprev + sigmoidf_(iz) * tanhf(gz);
        const float hn = sigmoidf_(oz) * tanhf(cn);
        out[bb * U + u]         = hn;
        out[B * U + bb * U + u] = cn;
    }
}

// ===========================================================================
// K5: nsc1 partial. 64 blocks = 32 unit-tiles (8 units) x 2 k-tiles (128).
// acts = h_new (from out). atomicAdd into g_ns (bias pre-initialized).
// ===========================================================================
__global__ __launch_bounds__(256, 1)
void k5_nsc1(const float* __restrict__ w1, const float* __restrict__ out)
{
    const int ut = blockIdx.x & 31;
    const int kt = blockIdx.x >> 5;
    const int t  = threadIdx.x;

    __shared__ float axs[64][132];
    __shared__ float wts[128][12];

    for (int i = t; i < 64 * 32; i += 256) {
        const int row = i >> 5;
        const int c4  = i & 31;
        const float4 v = *(const float4*)(out + row * U + kt * 128 + c4 * 4);
        *(float4*)&axs[row][c4 * 4] = v;
    }
    {
        const int row = t >> 1;
        const int h   = t & 1;
        const float4 w = *(const float4*)(w1 + (size_t)(kt * 128 + row) * U + ut * 8 + h * 4);
        *(float4*)&wts[row][h * 4] = w;
    }
    __syncthreads();

    const int u2 = t & 3;
    const int bp = t >> 2;
    float a0 = 0.f, a1 = 0.f, a2 = 0.f, a3 = 0.f;
    #pragma unroll 4
    for (int k = 0; k < 128; k += 2) {
        const float x0 = axs[bp][k];
        const float x1 = axs[bp][k + 1];
        const float2 w0 = *(const float2*)&wts[k][u2 * 2];
        const float2 w1v = *(const float2*)&wts[k + 1][u2 * 2];
        a0 += x0 * w0.x;  a1 += x0 * w0.y;
        a2 += x1 * w1v.x; a3 += x1 * w1v.y;
    }
    const int u = ut * 8 + u2 * 2;
    atomicAdd(&g_ns[bp * U + u],     a0 + a2);
    atomicAdd(&g_ns[bp * U + u + 1], a1 + a3);
}

// ===========================================================================
// K6: nsc2. next_section = sigmoid(relu(g_ns) @ W2 + b2). 64 blocks x 96.
// ===========================================================================
__global__ __launch_bounds__(96, 8)
void k6_nsc2(const float* __restrict__ w2, const float* __restrict__ b2,
             float* __restrict__ out)
{
    const int b = blockIdx.x;
    const int t = threadIdx.x;
    const int g = t >> 5;
    const int l = t & 31;

    const float* ns = g_ns + b * U;
    float s = 0.0f;
    #pragma unroll
    for (int k = l; k < U; k += 32)
        s += fmaxf(ns[k], 0.0f) * w2[k * 3 + g];
    #pragma unroll
    for (int o = 16; o > 0; o >>= 1)
        s += __shfl_down_sync(0xffffffffu, s, o);
    if (l == 0)
        out[2 * B * U + b * 3 + g] = sigmoidf_(s + b2[g]);
}

// ===========================================================================
extern "C" void kernel_launch(void* const* d_in, const int* in_sizes, int n_in,
                              void* d_out, int out_size)
{
    const float* image   = (const float*)d_in[0];
    const float* section = (const float*)d_in[1];
    const float* h0      = (const float*)d_in[2];
    const float* c0      = (const float*)d_in[3];
    const float* conv1_k = (const float*)d_in[4];
    const float* conv1_b = (const float*)d_in[5];
    const float* conv2_k = (const float*)d_in[6];
    const float* conv2_b = (const float*)d_in[7];
    const float* dense_w = (const float*)d_in[8];
    const float* dense_b = (const float*)d_in[9];
    const float* lstm_k  = (const float*)d_in[10];
    const float* lstm_rk = (const float*)d_in[11];
    const float* lstm_b  = (const float*)d_in[12];
    const float* nsc_w1  = (const float*)d_in[13];
    const float* nsc_b1  = (const float*)d_in[14];
    const float* nsc_w2  = (const float*)d_in[15];
    const float* nsc_b2  = (const float*)d_in[16];
    float* out = (float*)d_out;

    k1_front<<<B, 256>>>(image, section, conv1_k, conv1_b,
                         conv2_k, conv2_b, dense_b, nsc_b1);
    k2_dense<<<128, 256>>>(dense_w);
    k3_lstm_full<<<128, 256>>>(h0, c0, lstm_k, lstm_rk, lstm_b, out);
    k5_nsc1<<<64, 256>>>(nsc_w1, out);
    k6_nsc2<<<B, 96>>>(nsc_w2, nsc_b2, out);
}

// round 10
// speedup vs baseline: 1.1480x; 1.1480x over previous
#include <cuda_runtime.h>
#include <math.h>

// ---------------------------------------------------------------------------
// ImageSectionRNNCell — B=64, image 512x512x3, grid 16x16, U=256
// out layout: h_new[64*256] | c_new[64*256] | next_section[64*3]
//
// Round-7 structure (best: 27.1us) + two fixes:
//  * g_zp stored unit-major [b][u*4+gate] -> k4 reads 4 coalesced float4
//  * k5_nsc1 split into 4 k-tiles (128 blocks) instead of 2 (64)
//
//  K1 (64):  front (interp+conv1+conv2 -> g_xs) + bias-init g_y/g_ns
//  K2 (128): dense partial xs@dw -> g_y (atomicAdd, bias-pre-init)
//  K3 (128): LSTM partial (32 col-tile x 4 k-tile) -> g_zp (plain stores)
//  K4 (64):  gates: sum g_zp + lb, nonlinearity -> out h/c
//  K5 (128): nsc1 partial h@w1 -> g_ns (atomicAdd, bias-pre-init)
//  K6 (64):  nsc2 -> out section
// ---------------------------------------------------------------------------

#define B 64
#define U 256
#define IMGH 512
#define IMGW 512

__device__ float g_xs[B * 432];        // conv2 output (dense input)
__device__ float g_y [B * U];          // dense pre-act accumulator (bias-init)
__device__ float g_zp[4][B][4 * U];    // LSTM partials, unit-major [b][u*4+g]
__device__ float g_ns[B * U];          // nsc1 pre-act accumulator (bias-init)

__device__ __forceinline__ float sigmoidf_(float x) {
    return 1.0f / (1.0f + __expf(-x));
}

// ===========================================================================
// K1: bias-init g_y/g_ns + interpolate + conv1 + conv2 -> g_xs
// 64 blocks (one per batch) x 256 threads
// ===========================================================================
__global__ __launch_bounds__(256, 4)
void k1_front(const float* __restrict__ image,
              const float* __restrict__ section,
              const float* __restrict__ c1k, const float* __restrict__ c1b,
              const float* __restrict__ c2k, const float* __restrict__ c2b,
              const float* __restrict__ db,  const float* __restrict__ b1)
{
    const int b = blockIdx.x;
    const int t = threadIdx.x;

    g_y [b * U + t] = db[t];
    g_ns[b * U + t] = b1[t];

    __shared__ float sec[16 * 16 * 3];
    __shared__ float c1o[14 * 14 * 3];

    {
        const float s0 = section[b * 3 + 0];
        const float s1 = section[b * 3 + 1];
        const float ee = section[b * 3 + 2];
        const int i = t >> 4;
        const int j = t & 15;
        const float p0 = s0 + (float)i * (1.0f / 15.0f) * ee;
        const float p1 = s1 + (float)j * (1.0f / 15.0f) * ee;
        float fy = fminf(fmaxf(p0 * (float)(IMGH - 1), 0.0f), (float)(IMGH - 1));
        float fx = fminf(fmaxf(p1 * (float)(IMGW - 1), 0.0f), (float)(IMGW - 1));
        int y0 = (int)floorf(fy);
        int x0 = (int)floorf(fx);
        int y1 = min(y0 + 1, IMGH - 1);
        int x1 = min(x0 + 1, IMGW - 1);
        float wy = fy - (float)y0;
        float wx = fx - (float)x0;
        const float* img = image + (size_t)b * IMGH * IMGW * 3;
        const float* p00 = img + ((size_t)y0 * IMGW + x0) * 3;
        const float* p01 = img + ((size_t)y0 * IMGW + x1) * 3;
        const float* p10 = img + ((size_t)y1 * IMGW + x0) * 3;
        const float* p11 = img + ((size_t)y1 * IMGW + x1) * 3;
        #pragma unroll
        for (int c = 0; c < 3; c++) {
            float top = p00[c] * (1.0f - wx) + p01[c] * wx;
            float bot = p10[c] * (1.0f - wx) + p11[c] * wx;
            sec[(i * 16 + j) * 3 + c] = top * (1.0f - wy) + bot * wy;
        }
    }
    __syncthreads();

    if (t < 196) {
        const int oh = t / 14;
        const int ow = t - oh * 14;
        float a0 = c1b[0], a1 = c1b[1], a2 = c1b[2];
        #pragma unroll
        for (int kh = 0; kh < 3; kh++)
            #pragma unroll
            for (int kw = 0; kw < 3; kw++) {
                const float* s = &sec[((oh + kh) * 16 + (ow + kw)) * 3];
                const float* w = &c1k[(kh * 3 + kw) * 9];
                #pragma unroll
                for (int ic = 0; ic < 3; ic++) {
                    const float sv = s[ic];
                    a0 += sv * w[ic * 3 + 0];
                    a1 += sv * w[ic * 3 + 1];
                    a2 += sv * w[ic * 3 + 2];
                }
            }
        c1o[t * 3 + 0] = fmaxf(a0, 0.0f);
        c1o[t * 3 + 1] = fmaxf(a1, 0.0f);
        c1o[t * 3 + 2] = fmaxf(a2, 0.0f);
    }
    __syncthreads();

    if (t < 144) {
        const int oh = t / 12;
        const int ow = t - oh * 12;
        float a0 = c2b[0], a1 = c2b[1], a2 = c2b[2];
        #pragma unroll
        for (int kh = 0; kh < 3; kh++)
            #pragma unroll
            for (int kw = 0; kw < 3; kw++) {
                const float* s = &c1o[((oh + kh) * 14 + (ow + kw)) * 3];
                const float* w = &c2k[(kh * 3 + kw) * 9];
                #pragma unroll
                for (int ic = 0; ic < 3; ic++) {
                    const float sv = s[ic];
                    a0 += sv * w[ic * 3 + 0];
                    a1 += sv * w[ic * 3 + 1];
                    a2 += sv * w[ic * 3 + 2];
                }
            }
        float* dst = g_xs + b * 432 + t * 3;
        dst[0] = fmaxf(a0, 0.0f);
        dst[1] = fmaxf(a1, 0.0f);
        dst[2] = fmaxf(a2, 0.0f);
    }
}

// ===========================================================================
// K2: dense partial. 128 blocks = 32 unit-tiles (8 units) x 4 k-tiles (108).
// atomicAdd into g_y (bias pre-initialized). ReLU applied by consumer (K3).
// ===========================================================================
__global__ __launch_bounds__(256, 1)
void k2_dense(const float* __restrict__ dw)
{
    const int ut = blockIdx.x & 31;
    const int kt = blockIdx.x >> 5;
    const int t  = threadIdx.x;
    const int k0 = kt * 108;

    __shared__ float axs[64][112];
    __shared__ float wts[108][12];

    for (int i = t; i < 64 * 27; i += 256) {
        const int row = i / 27;
        const int c4  = i - row * 27;
        const float4 v = *(const float4*)(g_xs + row * 432 + k0 + c4 * 4);
        *(float4*)&axs[row][c4 * 4] = v;
    }
    if (t < 216) {
        const int row = t >> 1;
        const int h   = t & 1;
        const float4 w = *(const float4*)(dw + (size_t)(k0 + row) * U + ut * 8 + h * 4);
        *(float4*)&wts[row][h * 4] = w;
    }
    __syncthreads();

    const int u2 = t & 3;
    const int bp = t >> 2;
    float a0 = 0.f, a1 = 0.f, a2 = 0.f, a3 = 0.f;
    #pragma unroll 2
    for (int k = 0; k < 108; k += 2) {
        const float x0 = axs[bp][k];
        const float x1 = axs[bp][k + 1];
        const float2 w0 = *(const float2*)&wts[k][u2 * 2];
        const float2 w1 = *(const float2*)&wts[k + 1][u2 * 2];
        a0 += x0 * w0.x; a1 += x0 * w0.y;
        a2 += x1 * w1.x; a3 += x1 * w1.y;
    }
    const int u = ut * 8 + u2 * 2;
    atomicAdd(&g_y[bp * U + u],     a0 + a2);
    atomicAdd(&g_y[bp * U + u + 1], a1 + a3);
}

// ===========================================================================
// K3: LSTM partial. 128 blocks = 32 col-tiles (32 z-cols) x 4 k-tiles (128).
// kt<2 : acts = relu(g_y), weights = lstm_k;  kt>=2: acts = h0, w = lstm_rk.
// Partials -> g_zp[kt] in UNIT-MAJOR layout [b][u*4+gate] (plain stores).
// Dynamic smem: act[64][132] + wt[128][36] = 52224 bytes.
// ===========================================================================
__global__ __launch_bounds__(256, 1)
void k3_lstm(const float* __restrict__ h0,
             const float* __restrict__ lk, const float* __restrict__ lrk)
{
    extern __shared__ float dsm[];
    float (*act)[132] = (float(*)[132])dsm;               // 64 x 132
    float (*wt)[36]   = (float(*)[36])(dsm + 64 * 132);   // 128 x 36

    const int ct = blockIdx.x & 31;
    const int kt = blockIdx.x >> 5;
    const int t  = threadIdx.x;

    if (kt < 2) {
        const float* base = g_y + kt * 128;
        for (int i = t; i < 64 * 32; i += 256) {
            const int row = i >> 5;
            const int c4  = i & 31;
            float4 v = *(const float4*)(base + row * U + c4 * 4);
            v.x = fmaxf(v.x, 0.f); v.y = fmaxf(v.y, 0.f);
            v.z = fmaxf(v.z, 0.f); v.w = fmaxf(v.w, 0.f);
            *(float4*)&act[row][c4 * 4] = v;
        }
    } else {
        const float* base = h0 + (kt - 2) * 128;
        for (int i = t; i < 64 * 32; i += 256) {
            const int row = i >> 5;
            const int c4  = i & 31;
            const float4 v = *(const float4*)(base + row * U + c4 * 4);
            *(float4*)&act[row][c4 * 4] = v;
        }
    }
    {
        const float* wsrc = (kt < 2) ? (lk + (size_t)kt * 128 * 1024)
                                     : (lrk + (size_t)(kt - 2) * 128 * 1024);
        for (int i = t; i < 128 * 8; i += 256) {
            const int row = i >> 3;
            const int c4  = i & 7;
            const float4 w = *(const float4*)(wsrc + (size_t)row * 1024 + ct * 32 + c4 * 4);
            *(float4*)&wt[row][c4 * 4] = w;
        }
    }
    __syncthreads();

    const int c4 = t & 7;        // 4 cols: ct*32 + c4*4 ..
    const int bp = t >> 3;       // batches bp, bp+32
    float s00 = 0.f, s01 = 0.f, s02 = 0.f, s03 = 0.f;
    float s10 = 0.f, s11 = 0.f, s12 = 0.f, s13 = 0.f;
    #pragma unroll 4
    for (int k = 0; k < 128; k++) {
        const float a0 = act[bp][k];
        const float a1 = act[bp + 32][k];
        const float4 w = *(const float4*)&wt[k][c4 * 4];
        s00 += a0 * w.x; s01 += a0 * w.y; s02 += a0 * w.z; s03 += a0 * w.w;
        s10 += a1 * w.x; s11 += a1 * w.y; s12 += a1 * w.z; s13 += a1 * w.w;
    }
    // unit-major scatter: col = ct*32 + c4*4 + q -> [b][(u0+q)*4 + gate]
    const int col = ct * 32 + c4 * 4;
    const int gg  = col >> 8;        // gate index 0..3
    const int u0  = col & 255;       // unit index
    float* d0 = &g_zp[kt][bp][u0 * 4 + gg];
    d0[0]  = s00; d0[4]  = s01; d0[8]  = s02; d0[12] = s03;
    float* d1 = &g_zp[kt][bp + 32][u0 * 4 + gg];
    d1[0]  = s10; d1[4]  = s11; d1[8]  = s12; d1[12] = s13;
}

// ===========================================================================
// K4: gates. 64 blocks x 256 threads, thread = (batch b, unit u).
// Reads one float4 (all 4 gates) per k-tile — fully coalesced.
// ===========================================================================
__global__ __launch_bounds__(256, 4)
void k4_gates(const float* __restrict__ c0in, const float* __restrict__ lb,
              float* __restrict__ out)
{
    const int b = blockIdx.x;
    const int u = threadIdx.x;

    const float4 z0 = *(const float4*)&g_zp[0][b][u * 4];
    const float4 z1 = *(const float4*)&g_zp[1][b][u * 4];
    const float4 z2 = *(const float4*)&g_zp[2][b][u * 4];
    const float4 z3 = *(const float4*)&g_zp[3][b][u * 4];

    const float zi = z0.x + z1.x + z2.x + z3.x + lb[u];
    const float zf = z0.y + z1.y + z2.y + z3.y + lb[U + u];
    const float zg = z0.z + z1.z + z2.z + z3.z + lb[2 * U + u];
    const float zo = z0.w + z1.w + z2.w + z3.w + lb[3 * U + u];

    const float cprev = c0in[b * U + u];
    const float cn = sigmoidf_(zf) * cprev + sigmoidf_(zi) * tanhf(zg);
    const float hn = sigmoidf_(zo) * tanhf(cn);
    out[b * U + u]         = hn;
    out[B * U + b * U + u] = cn;
}

// ===========================================================================
// K5: nsc1 partial. 128 blocks = 32 unit-tiles (8 units) x 4 k-tiles (64).
// acts = h_new (from out). atomicAdd into g_ns (bias pre-initialized).
// ===========================================================================
__global__ __launch_bounds__(256, 1)
void k5_nsc1(const float* __restrict__ w1, const float* __restrict__ out)
{
    const int ut = blockIdx.x & 31;
    const int kt = blockIdx.x >> 5;      // 0..3, k-slice of 64
    const int t  = threadIdx.x;
    const int k0 = kt * 64;

    __shared__ float axs[64][68];
    __shared__ float wts[64][12];

    for (int i = t; i < 64 * 16; i += 256) {
        const int row = i >> 4;
        const int c4  = i & 15;
        const float4 v = *(const float4*)(out + row * U + k0 + c4 * 4);
        *(float4*)&axs[row][c4 * 4] = v;
    }
    if (t < 128) {
        const int row = t >> 1;
        const int h   = t & 1;
        const float4 w = *(const float4*)(w1 + (size_t)(k0 + row) * U + ut * 8 + h * 4);
        *(float4*)&wts[row][h * 4] = w;
    }
    __syncthreads();

    const int u2 = t & 3;
    const int bp = t >> 2;
    float a0 = 0.f, a1 = 0.f, a2 = 0.f, a3 = 0.f;
    #pragma unroll 4
    for (int k = 0; k < 64; k += 2) {
        const float x0 = axs[bp][k];
        const float x1 = axs[bp][k + 1];
        const float2 w0 = *(const float2*)&wts[k][u2 * 2];
        const float2 w1v = *(const float2*)&wts[k + 1][u2 * 2];
        a0 += x0 * w0.x;  a1 += x0 * w0.y;
        a2 += x1 * w1v.x; a3 += x1 * w1v.y;
    }
    const int u = ut * 8 + u2 * 2;
    atomicAdd(&g_ns[bp * U + u],     a0 + a2);
    atomicAdd(&g_ns[bp * U + u + 1], a1 + a3);
}

// ===========================================================================
// K6: nsc2. next_section = sigmoid(relu(g_ns) @ W2 + b2). 64 blocks x 96.
// ===========================================================================
__global__ __launch_bounds__(96, 8)
void k6_nsc2(const float* __restrict__ w2, const float* __restrict__ b2,
             float* __restrict__ out)
{
    const int b = blockIdx.x;
    const int t = threadIdx.x;
    const int g = t >> 5;
    const int l = t & 31;

    const float* ns = g_ns + b * U;
    float s = 0.0f;
    #pragma unroll
    for (int k = l; k < U; k += 32)
        s += fmaxf(ns[k], 0.0f) * w2[k * 3 + g];
    #pragma unroll
    for (int o = 16; o > 0; o >>= 1)
        s += __shfl_down_sync(0xffffffffu, s, o);
    if (l == 0)
        out[2 * B * U + b * 3 + g] = sigmoidf_(s + b2[g]);
}

// ===========================================================================
extern "C" void kernel_launch(void* const* d_in, const int* in_sizes, int n_in,
                              void* d_out, int out_size)
{
    const float* image   = (const float*)d_in[0];
    const float* section = (const float*)d_in[1];
    const float* h0      = (const float*)d_in[2];
    const float* c0      = (const float*)d_in[3];
    const float* conv1_k = (const float*)d_in[4];
    const float* conv1_b = (const float*)d_in[5];
    const float* conv2_k = (const float*)d_in[6];
    const float* conv2_b = (const float*)d_in[7];
    const float* dense_w = (const float*)d_in[8];
    const float* dense_b = (const float*)d_in[9];
    const float* lstm_k  = (const float*)d_in[10];
    const float* lstm_rk = (const float*)d_in[11];
    const float* lstm_b  = (const float*)d_in[12];
    const float* nsc_w1  = (const float*)d_in[13];
    const float* nsc_b1  = (const float*)d_in[14];
    const float* nsc_w2  = (const float*)d_in[15];
    const float* nsc_b2  = (const float*)d_in[16];
    float* out = (float*)d_out;

    static int attr_done = 0;
    if (!attr_done) {
        cudaFuncSetAttribute(k3_lstm,
                             cudaFuncAttributeMaxDynamicSharedMemorySize,
                             64 * 1024);
        attr_done = 1;
    }

    k1_front<<<B, 256>>>(image, section, conv1_k, conv1_b,
                         conv2_k, conv2_b, dense_b, nsc_b1);
    k2_dense<<<128, 256>>>(dense_w);
    k3_lstm<<<128, 256, (64 * 132 + 128 * 36) * 4>>>(h0, lstm_k, lstm_rk);
    k4_gates<<<B, 256>>>(c0, lstm_b, out);
    k5_nsc1<<<128, 256>>>(nsc_w1, out);
    k6_nsc2<<<B, 96>>>(nsc_w2, nsc_b2, out);
}